// round 3
// baseline (speedup 1.0000x reference)
#include <cuda_runtime.h>

#define N   2048
#define KM  192
#define NB  16
#define T   256
#define RPB (N/NB)   // 128 rows per block

// ---------------- device state (no allocations allowed) ----------------
__device__ float g_V[2][N*KM];     // ping-pong basis, row-major stride KM
__device__ float g_p[2][N];        // ping-pong row norms^2
__device__ int   g_cols[KM];
__device__ int   g_k;
__device__ int   g_kk;
__device__ unsigned g_kl0, g_kl1;  // k_loop key
__device__ unsigned g_arrive = 0;
__device__ volatile unsigned g_gen = 0;

// ---------------- threefry2x32 block (exact JAX rotation schedule) ----------------
__device__ __forceinline__ void tf2x32(unsigned k0, unsigned k1,
                                       unsigned c0, unsigned c1,
                                       unsigned &o0, unsigned &o1) {
    unsigned ks2 = k0 ^ k1 ^ 0x1BD11BDAu;
    unsigned x0 = c0 + k0, x1 = c1 + k1;
#define RR(r) { x0 += x1; x1 = (x1 << (r)) | (x1 >> (32 - (r))); x1 ^= x0; }
    RR(13) RR(15) RR(26) RR(6)   x0 += k1;  x1 += ks2 + 1u;
    RR(17) RR(29) RR(16) RR(24)  x0 += ks2; x1 += k0 + 2u;
    RR(13) RR(15) RR(26) RR(6)   x0 += k0;  x1 += k1 + 3u;
    RR(17) RR(29) RR(16) RR(24)  x0 += k1;  x1 += ks2 + 4u;
    RR(13) RR(15) RR(26) RR(6)   x0 += ks2; x1 += k0 + 5u;
#undef RR
    o0 = x0; o1 = x1;
}

// partitionable random_bits(key, 32, shape): per-element counter (0, i), XOR lanes
__device__ __forceinline__ unsigned tf_bits32(unsigned k0, unsigned k1, unsigned i) {
    unsigned a, b;
    tf2x32(k0, k1, 0u, i, a, b);
    return a ^ b;
}

__device__ __forceinline__ float u01(unsigned b) {
    // jax uniform: bitcast((bits>>9)|0x3f800000) - 1.0
    return __uint_as_float((b >> 9) | 0x3f800000u) - 1.0f;
}

// ---------------- grid barrier (sense via generation counter) ----------------
__device__ __forceinline__ void grid_sync(unsigned &genL) {
    __syncthreads();
    if (threadIdx.x == 0) {
        __threadfence();
        unsigned t = atomicAdd(&g_arrive, 1u);
        if (t == NB - 1) {
            g_arrive = 0;
            __threadfence();
            g_gen = genL + 1;
        } else {
            while (g_gen == genL) { __nanosleep(32); }
        }
        __threadfence();
    }
    __syncthreads();
    genL++;
}

__global__ void __launch_bounds__(T, 1)
dpp_kernel(const float* __restrict__ e, const float* __restrict__ v,
           const int* __restrict__ seedp, float* __restrict__ out) {
    const int tid = threadIdx.x, bid = blockIdx.x;

    __shared__ float sa[KM];
    __shared__ int   s_cols[KM];
    __shared__ float sred[T];
    __shared__ float sscan[T];
    __shared__ int   s_item;
    __shared__ float s_u, s_tau, s_sh;
    __shared__ unsigned s_k0, s_k1;
    __shared__ unsigned char sf[N];
    __shared__ int   sc[T];

    unsigned genL = g_gen;   // snapshot generation (read precedes our first arrive)

    // ---------------- phase 0: zero output, PRNG thinning, column compaction ----
    if (tid < RPB) out[bid * RPB + tid] = 0.0f;

    if (bid == 0) {
        if (tid == 0) {
            // jax.random.key(seed): (0, seed). partitionable split(key, 2):
            // key_i = full block output with counter (0, i)
            unsigned key0 = 0u, key1 = (unsigned)seedp[0];
            unsigned a0, b0, a1, b1;
            tf2x32(key0, key1, 0u, 0u, a0, b0);   // k_idx  = block(key,(0,0))
            tf2x32(key0, key1, 0u, 1u, a1, b1);   // k_loop = block(key,(0,1))
            s_k0 = a0; s_k1 = b0;
            g_kl0 = a1; g_kl1 = b1;
        }
        __syncthreads();
        unsigned kk0 = s_k0, kk1 = s_k1;
        for (int pp = tid; pp < N; pp += T) {
            float ev = e[pp];
            float thr = __fdiv_rn(ev, __fadd_rn(ev, 1.0f));
            sf[pp] = (u01(tf_bits32(kk0, kk1, (unsigned)pp)) < thr) ? 1 : 0;
        }
        __syncthreads();
        // stable compaction of selected indices (== argsort(~index)[:kk])
        int base = tid * 8, cnt = 0;
        #pragma unroll
        for (int j = 0; j < 8; j++) cnt += sf[base + j];
        sc[tid] = cnt; __syncthreads();
        for (int off = 1; off < T; off <<= 1) {
            int val = sc[tid];
            int add = (tid >= off) ? sc[tid - off] : 0;
            __syncthreads();
            sc[tid] = val + add;
            __syncthreads();
        }
        int excl = sc[tid] - cnt, total = sc[T - 1];
        int pos = excl;
        for (int j = 0; j < 8; j++) {
            if (sf[base + j]) { if (pos < KM) g_cols[pos] = base + j; pos++; }
        }
        if (tid == 0) { g_k = total; g_kk = total < KM ? total : KM; }
    }

    grid_sync(genL);

    const int kk = g_kk;
    const int kfull = g_k;
    unsigned kl0 = g_kl0, kl1 = g_kl1;

    for (int j = tid; j < KM; j += T) s_cols[j] = (j < kk) ? g_cols[j] : 0;
    __syncthreads();

    // ---------------- phase 1: gather V0 columns + initial p ----------------
    if (tid < RPB) {
        int r = bid * RPB + tid;
        const float* vr = v + (size_t)r * N;
        float* Vr = g_V[0] + r * KM;
        float acc = 0.f;
        #pragma unroll 4
        for (int j = 0; j < kk; j++) {
            float x = vr[s_cols[j]];
            Vr[j] = x;
            acc = fmaf(x, x, acc);
        }
        g_p[0][r] = acc;
    }

    // ---------------- main sequential loop: one grid barrier per iteration ----
    for (int i = 0; i < kk; i++) {
        grid_sync(genL);                  // V[par], p[par] ready chip-wide
        const int m = kk - i;
        const int par = i & 1;
        const float* pc = g_p[par];

        if (tid == 0) {
            // u_i = uniform(fold_in(k_loop, i)):
            // fold_in -> block(k_loop,(0,i)) as new key; scalar bits -> lane XOR
            unsigned f0, f1, w0, w1;
            tf2x32(kl0, kl1, 0u, (unsigned)i, f0, f1);
            tf2x32(f0, f1, 0u, 0u, w0, w1);
            s_u = u01(w0 ^ w1);
            s_item = 0x7FFFFFFF;
        }
        __syncthreads();

        // ---- total S = sum(p) ----
        float pv[8]; float ls = 0.f;
        int base = tid * 8;
        #pragma unroll
        for (int j = 0; j < 8; j++) { pv[j] = pc[base + j]; ls += pv[j]; }
        sred[tid] = ls; __syncthreads();
        for (int off = T / 2; off > 0; off >>= 1) {
            if (tid < off) sred[tid] += sred[tid + off];
            __syncthreads();
        }
        float S = sred[0];

        // ---- item = argmax(u < cumsum(p/S)) ----
        float qv[8]; float lq = 0.f;
        #pragma unroll
        for (int j = 0; j < 8; j++) { qv[j] = __fdiv_rn(pv[j], S); lq += qv[j]; }
        sscan[tid] = lq; __syncthreads();
        for (int off = 1; off < T; off <<= 1) {
            float val = sscan[tid];
            float add = (tid >= off) ? sscan[tid - off] : 0.f;
            __syncthreads();
            sscan[tid] = val + add;
            __syncthreads();
        }
        float run = (tid > 0) ? sscan[tid - 1] : 0.f;
        float u = s_u;
        int found = 0x7FFFFFFF;
        #pragma unroll
        for (int j = 0; j < 8; j++) {
            run += qv[j];
            if (found == 0x7FFFFFFF && run > u) found = base + j;
        }
        if (found != 0x7FFFFFFF) atomicMin(&s_item, found);
        __syncthreads();
        int item = (s_item == 0x7FFFFFFF) ? 0 : s_item;   // argmax of all-False -> 0
        if (bid == 0 && tid == 0) out[item] = 1.0f;

        if (m == 1) continue;   // reference keeps V unchanged when m==1

        // ---- a = V[item,:], n2 = ||a||^2 ----
        const float* Vit = g_V[par] + item * KM;
        for (int j = tid; j < m; j += T) sa[j] = Vit[j];
        __syncthreads();
        float pa = 0.f;
        for (int j = tid; j < m; j += T) pa = fmaf(sa[j], sa[j], pa);
        sred[tid] = pa; __syncthreads();
        for (int off = T / 2; off > 0; off >>= 1) {
            if (tid < off) sred[tid] += sred[tid + off];
            __syncthreads();
        }
        if (tid == 0) {
            float n2  = sred[0];
            float nrm = sqrtf(n2);
            float al  = sa[m - 1];
            s_sh  = (al >= 0.f) ? nrm : -nrm;              // Householder shift
            float den = fmaf(fabsf(al), nrm, n2);          // ||u||^2 / 2
            s_tau = (den > 0.f) ? (1.0f / den) : 0.f;
        }
        __syncthreads();

        // ---- Householder sweep: V' = V·H, drop last column; new p ----
        if (tid < RPB) {
            int r = bid * RPB + tid;
            const float* vc = g_V[par] + r * KM;
            float* vn = g_V[par ^ 1] + r * KM;
            float t = 0.f;
            #pragma unroll 4
            for (int j = 0; j < m; j++) t = fmaf(vc[j], sa[j], t);
            float w = s_tau * fmaf(s_sh, vc[m - 1], t);
            float acc = 0.f;
            #pragma unroll 4
            for (int j = 0; j < m - 1; j++) {
                float x = fmaf(-w, sa[j], vc[j]);
                vn[j] = x;
                acc = fmaf(x, x, acc);
            }
            g_p[par ^ 1][r] = acc;
        }
    }

    // k == n -> all ones (safe: every concurrent write is 1.0f)
    if (kfull == N) {
        if (tid < RPB) out[bid * RPB + tid] = 1.0f;
    }
}

extern "C" void kernel_launch(void* const* d_in, const int* in_sizes, int n_in,
                              void* d_out, int out_size) {
    const float* e    = (const float*)d_in[0];
    const float* v    = (const float*)d_in[1];
    const int*   seed = (const int*)d_in[2];
    (void)in_sizes; (void)n_in; (void)out_size;
    dpp_kernel<<<NB, T>>>(e, v, seed, (float*)d_out);
}

// round 7
// speedup vs baseline: 1.3753x; 1.3753x over previous
#include <cuda_runtime.h>
#include <cstdint>

#define N   2048
#define KM  192
#define NB  16
#define T   256
#define RPB (N/NB)   // 128 rows per block

// ---------------- device state (no allocations allowed) ----------------
__device__ float g_V[2][N*KM];     // ping-pong basis, row-major stride KM
__device__ float g_p[2][N];        // ping-pong row norms^2
__device__ float g_bs[2][NB];      // ping-pong per-block p sums
__device__ int   g_cols[KM];
__device__ int   g_k;
__device__ int   g_kk;
__device__ unsigned g_kl0, g_kl1;  // k_loop key
__device__ unsigned g_base;        // flag base for this launch
__device__ unsigned g_flag[NB];    // monotonic publish counters (zero at load)
__device__ unsigned g_arrive = 0;
__device__ volatile unsigned g_gen = 0;

// ---------------- acquire/release helpers ----------------
__device__ __forceinline__ unsigned ld_acq(const unsigned* p) {
    unsigned v;
    asm volatile("ld.acquire.gpu.u32 %0, [%1];" : "=r"(v) : "l"(p) : "memory");
    return v;
}
__device__ __forceinline__ void st_rel(unsigned* p, unsigned v) {
    asm volatile("st.release.gpu.u32 [%0], %1;" :: "l"(p), "r"(v) : "memory");
}

// ---------------- threefry2x32 block (exact JAX rotation schedule) ----------------
__device__ __forceinline__ void tf2x32(unsigned k0, unsigned k1,
                                       unsigned c0, unsigned c1,
                                       unsigned &o0, unsigned &o1) {
    unsigned ks2 = k0 ^ k1 ^ 0x1BD11BDAu;
    unsigned x0 = c0 + k0, x1 = c1 + k1;
#define RR(r) { x0 += x1; x1 = (x1 << (r)) | (x1 >> (32 - (r))); x1 ^= x0; }
    RR(13) RR(15) RR(26) RR(6)   x0 += k1;  x1 += ks2 + 1u;
    RR(17) RR(29) RR(16) RR(24)  x0 += ks2; x1 += k0 + 2u;
    RR(13) RR(15) RR(26) RR(6)   x0 += k0;  x1 += k1 + 3u;
    RR(17) RR(29) RR(16) RR(24)  x0 += k1;  x1 += ks2 + 4u;
    RR(13) RR(15) RR(26) RR(6)   x0 += ks2; x1 += k0 + 5u;
#undef RR
    o0 = x0; o1 = x1;
}
__device__ __forceinline__ unsigned tf_bits32(unsigned k0, unsigned k1, unsigned i) {
    unsigned a, b;
    tf2x32(k0, k1, 0u, i, a, b);
    return a ^ b;
}
__device__ __forceinline__ float u01(unsigned b) {
    return __uint_as_float((b >> 9) | 0x3f800000u) - 1.0f;
}

// ---------------- one-time grid barrier (generation-based, replay-safe) ----------
__device__ __forceinline__ void grid_sync(unsigned &genL) {
    __syncthreads();
    if (threadIdx.x == 0) {
        __threadfence();
        unsigned t = atomicAdd(&g_arrive, 1u);
        if (t == NB - 1) {
            g_arrive = 0;
            __threadfence();
            g_gen = genL + 1;
        } else {
            while (g_gen == genL) { __nanosleep(32); }
        }
        __threadfence();
    }
    __syncthreads();
    genL++;
}

__global__ void __launch_bounds__(T, 1)
dpp_kernel(const float* __restrict__ e, const float* __restrict__ v,
           const int* __restrict__ seedp, float* __restrict__ out) {
    const int tid = threadIdx.x, bid = blockIdx.x;
    const int lane = tid & 31, wid = tid >> 5;

    __shared__ float sa[KM];
    __shared__ int   s_cols[KM];
    __shared__ float swt[8], swt2[8], swred[8];
    __shared__ int   swcand[8];
    __shared__ float s_S;
    __shared__ int   s_item;
    __shared__ unsigned s_k0, s_k1;
    __shared__ unsigned char sf[N];
    __shared__ int   sc[T];

    unsigned genL = g_gen;   // snapshot (read precedes our first arrive)

    // ---------------- phase 0: zero output, PRNG thinning, column compaction ----
    if (tid < RPB) out[bid * RPB + tid] = 0.0f;

    if (bid == 0) {
        if (tid == 0) {
            g_base = g_flag[0];   // all flags equal after any completed launch
            // jax.random.key(seed) = (0, seed); partitionable split(key,2):
            // key_i = full block output with counter (0, i)
            unsigned key0 = 0u, key1 = (unsigned)seedp[0];
            unsigned a0, b0, a1, b1;
            tf2x32(key0, key1, 0u, 0u, a0, b0);   // k_idx
            tf2x32(key0, key1, 0u, 1u, a1, b1);   // k_loop
            s_k0 = a0; s_k1 = b0;
            g_kl0 = a1; g_kl1 = b1;
        }
        __syncthreads();
        unsigned kk0 = s_k0, kk1 = s_k1;
        for (int pp = tid; pp < N; pp += T) {
            float ev = e[pp];
            float thr = __fdiv_rn(ev, __fadd_rn(ev, 1.0f));
            sf[pp] = (u01(tf_bits32(kk0, kk1, (unsigned)pp)) < thr) ? 1 : 0;
        }
        __syncthreads();
        int base8 = tid * 8, cnt = 0;
        #pragma unroll
        for (int j = 0; j < 8; j++) cnt += sf[base8 + j];
        sc[tid] = cnt; __syncthreads();
        for (int off = 1; off < T; off <<= 1) {
            int val = sc[tid];
            int add = (tid >= off) ? sc[tid - off] : 0;
            __syncthreads();
            sc[tid] = val + add;
            __syncthreads();
        }
        int excl = sc[tid] - cnt, total = sc[T - 1];
        int pos = excl;
        for (int j = 0; j < 8; j++) {
            if (sf[base8 + j]) { if (pos < KM) g_cols[pos] = base8 + j; pos++; }
        }
        if (tid == 0) { g_k = total; g_kk = total < KM ? total : KM; }
    }

    grid_sync(genL);   // g_cols/g_kk/g_kl*/g_base visible (threadfence flushes L1)

    const int kk = g_kk;
    const int kfull = g_k;
    const unsigned kl0 = g_kl0, kl1 = g_kl1;
    const unsigned base = g_base;

    for (int j = tid; j < KM; j += T) s_cols[j] = (j < kk) ? g_cols[j] : 0;
    __syncthreads();

    // ---------------- phase 1: gather V0 (2 threads/row) + p + publish ----------
    {
        int pr = tid >> 1, h = tid & 1;
        int r = bid * RPB + pr;
        const float* vr = v + (size_t)r * N;
        float* Vr = g_V[0] + (size_t)r * KM;
        float acc = 0.f;
        #pragma unroll 4
        for (int j = h; j < kk; j += 2) {
            float x = vr[s_cols[j]];
            Vr[j] = x;
            acc = fmaf(x, x, acc);
        }
        float accT = acc + __shfl_xor_sync(0xFFFFFFFFu, acc, 1);
        if (h == 0) g_p[0][r] = accT;
        float val = h ? 0.f : accT;
        #pragma unroll
        for (int o = 16; o; o >>= 1) val += __shfl_down_sync(0xFFFFFFFFu, val, o);
        if (lane == 0) swred[wid] = val;
    }
    __threadfence();
    __syncthreads();
    if (tid == 0) {
        float s = 0.f;
        #pragma unroll
        for (int w2 = 0; w2 < 8; w2++) s += swred[w2];
        g_bs[0][bid] = s;
        st_rel(&g_flag[bid], base + 1u);
    }

    // ---------------- main loop: flag-fused sync, one L2 hop chain per iter -----
    for (int i = 0; i < kk; i++) {
        const int m = kk - i;
        const int par = i & 1;

        // u_i = uniform(fold_in(k_loop, i)) — redundant per thread, no bars
        float u;
        {
            unsigned f0, f1, w0, w1;
            tf2x32(kl0, kl1, 0u, (unsigned)i, f0, f1);
            tf2x32(f0, f1, 0u, 0u, w0, w1);
            u = u01(w0 ^ w1);
        }

        // warp 0: acquire-poll all publish flags, then read block sums -> S
        if (tid < 32) {
            unsigned tgt = base + 1u + (unsigned)i;
            bool need = tid < NB;
            for (;;) {
                unsigned fv = need ? ld_acq(&g_flag[tid]) : tgt;
                if (__all_sync(0xFFFFFFFFu, fv >= tgt)) break;
                __nanosleep(20);
            }
            float bsv = need ? __ldcg(&g_bs[par][tid]) : 0.f;
            #pragma unroll
            for (int o = 16; o; o >>= 1) bsv += __shfl_xor_sync(0xFFFFFFFFu, bsv, o);
            if (tid == 0) s_S = bsv;
        }
        __syncthreads();
        const float S = s_S;

        // ---- item = first index with cumsum(p_j/S) > u (hierarchical shfl scan) ----
        int base8 = tid * 8;
        float4 pA = __ldcg((const float4*)(g_p[par] + base8));
        float4 pB = __ldcg((const float4*)(g_p[par] + base8 + 4));
        float q[8];
        q[0] = __fdiv_rn(pA.x, S); q[1] = __fdiv_rn(pA.y, S);
        q[2] = __fdiv_rn(pA.z, S); q[3] = __fdiv_rn(pA.w, S);
        q[4] = __fdiv_rn(pB.x, S); q[5] = __fdiv_rn(pB.y, S);
        q[6] = __fdiv_rn(pB.z, S); q[7] = __fdiv_rn(pB.w, S);
        float lq = ((q[0]+q[1])+(q[2]+q[3])) + ((q[4]+q[5])+(q[6]+q[7]));
        float inc = lq;
        #pragma unroll
        for (int o = 1; o < 32; o <<= 1) {
            float nv = __shfl_up_sync(0xFFFFFFFFu, inc, o);
            if (lane >= o) inc += nv;
        }
        float wexcl = inc - lq;
        if (lane == 31) swt[wid] = inc;
        __syncthreads();
        if (tid < 8) {
            float vv = swt[tid];
            float inc2 = vv;
            #pragma unroll
            for (int o = 1; o < 8; o <<= 1) {
                float nv = __shfl_up_sync(0xFFu, inc2, o);
                if (tid >= o) inc2 += nv;
            }
            swt2[tid] = inc2 - vv;
        }
        __syncthreads();
        float run = swt2[wid] + wexcl;
        int c = 0x7FFFFFFF;
        #pragma unroll
        for (int j = 0; j < 8; j++) {
            run += q[j];
            if (c == 0x7FFFFFFF && run > u) c = base8 + j;
        }
        unsigned bm = __ballot_sync(0xFFFFFFFFu, c != 0x7FFFFFFF);
        if (bm ? (lane == __ffs(bm) - 1) : (lane == 0)) swcand[wid] = c;
        __syncthreads();
        if (tid == 0) {
            int it = 0x7FFFFFFF;
            #pragma unroll
            for (int w2 = 0; w2 < 8; w2++) it = min(it, swcand[w2]);
            if (it == 0x7FFFFFFF) it = 0;   // argmax(all-False) -> 0
            s_item = it;
            if (bid == 0) out[it] = 1.0f;
        }
        __syncthreads();
        const int item = s_item;

        if (m == 1) continue;   // reference keeps V unchanged when m==1; no publish

        // ---- a-row to smem + redundant per-thread tau/sh (no extra reductions) ----
        const float* arow = g_V[par] + (size_t)item * KM;
        if (tid < m) sa[tid] = __ldcg(arow + tid);
        float n2 = __ldcg(&g_p[par][item]);       // == ||a||^2 (published row norm)
        float al = __ldcg(arow + (m - 1));
        float nrm = sqrtf(n2);
        float sh = (al >= 0.f) ? nrm : -nrm;
        float den = fmaf(fabsf(al), nrm, n2);     // ||u||^2 / 2
        float tau = (den > 0.f) ? (1.0f / den) : 0.f;
        __syncthreads();

        // ---- Householder sweep, 2 threads/row (parity split), 4-way ILP ----
        {
            int pr = tid >> 1, h = tid & 1;
            int r = bid * RPB + pr;
            const float* vc = g_V[par] + (size_t)r * KM;
            float* vn = g_V[par ^ 1] + (size_t)r * KM;
            float t0 = 0.f, t1 = 0.f, t2 = 0.f, t3 = 0.f;
            int j = h;
            for (; j + 6 < m; j += 8) {
                t0 = fmaf(vc[j],     sa[j],     t0);
                t1 = fmaf(vc[j + 2], sa[j + 2], t1);
                t2 = fmaf(vc[j + 4], sa[j + 4], t2);
                t3 = fmaf(vc[j + 6], sa[j + 6], t3);
            }
            for (; j < m; j += 2) t0 = fmaf(vc[j], sa[j], t0);
            float t = (t0 + t1) + (t2 + t3);
            t += __shfl_xor_sync(0xFFFFFFFFu, t, 1);
            float w = tau * fmaf(sh, vc[m - 1], t);
            float a0 = 0.f, a1 = 0.f;
            j = h;
            for (; j + 2 < m - 1; j += 4) {
                float x0 = fmaf(-w, sa[j], vc[j]);         vn[j] = x0;     a0 = fmaf(x0, x0, a0);
                float x1 = fmaf(-w, sa[j + 2], vc[j + 2]); vn[j + 2] = x1; a1 = fmaf(x1, x1, a1);
            }
            for (; j < m - 1; j += 2) {
                float x = fmaf(-w, sa[j], vc[j]); vn[j] = x; a0 = fmaf(x, x, a0);
            }
            float acc = a0 + a1;
            float accT = acc + __shfl_xor_sync(0xFFFFFFFFu, acc, 1);
            if (h == 0) g_p[par ^ 1][r] = accT;
            float val = h ? 0.f : accT;
            #pragma unroll
            for (int o = 16; o; o >>= 1) val += __shfl_down_sync(0xFFFFFFFFu, val, o);
            if (lane == 0) swred[wid] = val;
        }
        __threadfence();
        __syncthreads();
        if (tid == 0) {
            float s = 0.f;
            #pragma unroll
            for (int w2 = 0; w2 < 8; w2++) s += swred[w2];
            g_bs[par ^ 1][bid] = s;
            st_rel(&g_flag[bid], base + 2u + (unsigned)i);
        }
    }

    // k == n -> all ones (concurrent writes are all 1.0f; benign)
    if (kfull == N) {
        if (tid < RPB) out[bid * RPB + tid] = 1.0f;
    }
}

extern "C" void kernel_launch(void* const* d_in, const int* in_sizes, int n_in,
                              void* d_out, int out_size) {
    const float* e    = (const float*)d_in[0];
    const float* v    = (const float*)d_in[1];
    const int*   seed = (const int*)d_in[2];
    (void)in_sizes; (void)n_in; (void)out_size;
    dpp_kernel<<<NB, T>>>(e, v, seed, (float*)d_out);
}

// round 8
// speedup vs baseline: 1.5657x; 1.1384x over previous
#include <cuda_runtime.h>
#include <cstdint>

#define N   2048
#define KM  192
#define NB  16
#define T   256
#define RPB (N/NB)   // 128 rows per block

typedef unsigned long long u64;

// ---------------- device state (no allocations allowed) ----------------
__device__ float g_V[2][N*KM];     // ping-pong basis, row-major stride KM
__device__ float g_p[2][N];        // ping-pong row norms^2
__device__ int   g_cols[KM];
__device__ int   g_k;
__device__ int   g_kk;
__device__ unsigned g_kl0, g_kl1;  // k_loop key
__device__ unsigned g_base;        // flag base for this launch
__device__ u64   g_flag2[NB];      // packed {counter:32, blocksum_bits:32}, zero at load
__device__ unsigned g_arrive = 0;
__device__ volatile unsigned g_gen = 0;

// ---------------- acquire/release helpers ----------------
__device__ __forceinline__ u64 ld_acq64(const u64* p) {
    u64 v;
    asm volatile("ld.acquire.gpu.u64 %0, [%1];" : "=l"(v) : "l"(p) : "memory");
    return v;
}
__device__ __forceinline__ void st_rel64(u64* p, u64 v) {
    asm volatile("st.release.gpu.u64 [%0], %1;" :: "l"(p), "l"(v) : "memory");
}

// ---------------- threefry2x32 block (exact JAX rotation schedule) ----------------
__device__ __forceinline__ void tf2x32(unsigned k0, unsigned k1,
                                       unsigned c0, unsigned c1,
                                       unsigned &o0, unsigned &o1) {
    unsigned ks2 = k0 ^ k1 ^ 0x1BD11BDAu;
    unsigned x0 = c0 + k0, x1 = c1 + k1;
#define RR(r) { x0 += x1; x1 = (x1 << (r)) | (x1 >> (32 - (r))); x1 ^= x0; }
    RR(13) RR(15) RR(26) RR(6)   x0 += k1;  x1 += ks2 + 1u;
    RR(17) RR(29) RR(16) RR(24)  x0 += ks2; x1 += k0 + 2u;
    RR(13) RR(15) RR(26) RR(6)   x0 += k0;  x1 += k1 + 3u;
    RR(17) RR(29) RR(16) RR(24)  x0 += k1;  x1 += ks2 + 4u;
    RR(13) RR(15) RR(26) RR(6)   x0 += ks2; x1 += k0 + 5u;
#undef RR
    o0 = x0; o1 = x1;
}
__device__ __forceinline__ unsigned tf_bits32(unsigned k0, unsigned k1, unsigned i) {
    unsigned a, b;
    tf2x32(k0, k1, 0u, i, a, b);
    return a ^ b;
}
__device__ __forceinline__ float u01(unsigned b) {
    return __uint_as_float((b >> 9) | 0x3f800000u) - 1.0f;
}

// ---------------- one-time grid barrier (generation-based, replay-safe) ----------
__device__ __forceinline__ void grid_sync(unsigned &genL) {
    __syncthreads();
    if (threadIdx.x == 0) {
        __threadfence();
        unsigned t = atomicAdd(&g_arrive, 1u);
        if (t == NB - 1) {
            g_arrive = 0;
            __threadfence();
            g_gen = genL + 1;
        } else {
            while (g_gen == genL) { __nanosleep(32); }
        }
        __threadfence();
    }
    __syncthreads();
    genL++;
}

__global__ void __launch_bounds__(T, 1)
dpp_kernel(const float* __restrict__ e, const float* __restrict__ v,
           const int* __restrict__ seedp, float* __restrict__ out) {
    const int tid = threadIdx.x, bid = blockIdx.x;
    const int lane = tid & 31, wid = tid >> 5;

    __shared__ float sa[KM];
    __shared__ int   s_cols[KM];
    __shared__ float swt[8], swt2[8], swred[8];
    __shared__ float s_S;
    __shared__ int   s_item;
    __shared__ unsigned s_k0, s_k1;
    __shared__ unsigned char sf[N];
    __shared__ int   sc[T];

    unsigned genL = g_gen;   // snapshot (read precedes our first arrive)

    // ---------------- phase 0: zero output, PRNG thinning, column compaction ----
    if (tid < RPB) out[bid * RPB + tid] = 0.0f;

    if (bid == 0) {
        if (tid == 0) {
            g_base = (unsigned)(g_flag2[0] >> 32);   // flags equal after any launch
            // jax.random.key(seed) = (0, seed); partitionable split(key,2):
            // key_i = full block output with counter (0, i)
            unsigned key0 = 0u, key1 = (unsigned)seedp[0];
            unsigned a0, b0, a1, b1;
            tf2x32(key0, key1, 0u, 0u, a0, b0);   // k_idx
            tf2x32(key0, key1, 0u, 1u, a1, b1);   // k_loop
            s_k0 = a0; s_k1 = b0;
            g_kl0 = a1; g_kl1 = b1;
        }
        __syncthreads();
        unsigned kk0 = s_k0, kk1 = s_k1;
        for (int pp = tid; pp < N; pp += T) {
            float ev = e[pp];
            float thr = __fdiv_rn(ev, __fadd_rn(ev, 1.0f));
            sf[pp] = (u01(tf_bits32(kk0, kk1, (unsigned)pp)) < thr) ? 1 : 0;
        }
        __syncthreads();
        int base8 = tid * 8, cnt = 0;
        #pragma unroll
        for (int j = 0; j < 8; j++) cnt += sf[base8 + j];
        sc[tid] = cnt; __syncthreads();
        for (int off = 1; off < T; off <<= 1) {
            int val = sc[tid];
            int add = (tid >= off) ? sc[tid - off] : 0;
            __syncthreads();
            sc[tid] = val + add;
            __syncthreads();
        }
        int excl = sc[tid] - cnt, total = sc[T - 1];
        int pos = excl;
        for (int j = 0; j < 8; j++) {
            if (sf[base8 + j]) { if (pos < KM) g_cols[pos] = base8 + j; pos++; }
        }
        if (tid == 0) { g_k = total; g_kk = total < KM ? total : KM; }
    }

    grid_sync(genL);   // g_cols/g_kk/g_kl*/g_base visible (threadfence flushes)

    const int kk = g_kk;
    const int kfull = g_k;
    const unsigned kl0 = g_kl0, kl1 = g_kl1;
    const unsigned base = g_base;

    for (int j = tid; j < KM; j += T) s_cols[j] = (j < kk) ? g_cols[j] : 0;
    __syncthreads();

    // ---------------- phase 1: gather V0 (2 threads/row) + p + publish ----------
    {
        int pr = tid >> 1, h = tid & 1;
        int r = bid * RPB + pr;
        const float* vr = v + (size_t)r * N;
        float* Vr = g_V[0] + (size_t)r * KM;
        float acc = 0.f;
        #pragma unroll 4
        for (int j = h; j < kk; j += 2) {
            float x = vr[s_cols[j]];
            Vr[j] = x;
            acc = fmaf(x, x, acc);
        }
        float accT = acc + __shfl_xor_sync(0xFFFFFFFFu, acc, 1);
        if (h == 0) g_p[0][r] = accT;
        float val = h ? 0.f : accT;
        #pragma unroll
        for (int o = 16; o; o >>= 1) val += __shfl_down_sync(0xFFFFFFFFu, val, o);
        if (lane == 0) swred[wid] = val;
    }
    __syncthreads();
    if (tid == 0) {
        float s = 0.f;
        #pragma unroll
        for (int w2 = 0; w2 < 8; w2++) s += swred[w2];
        st_rel64(&g_flag2[bid], ((u64)(base + 1u) << 32) | (u64)__float_as_uint(s));
    }

    // ---------------- main loop: packed flag sync, minimal serial L2 hops ------
    for (int i = 0; i < kk; i++) {
        const int m = kk - i;
        const int par = i & 1;

        // u_i = uniform(fold_in(k_loop, i)) — redundant per thread (overlaps spin)
        float u;
        {
            unsigned f0, f1, w0, w1;
            tf2x32(kl0, kl1, 0u, (unsigned)i, f0, f1);
            tf2x32(f0, f1, 0u, 0u, w0, w1);
            u = u01(w0 ^ w1);
        }

        // every warp polls the packed flags itself (busy spin, acquire)
        const unsigned tgt = base + 1u + (unsigned)i;
        const bool need = lane < NB;
        u64 fv;
        for (;;) {
            fv = need ? ld_acq64(&g_flag2[lane]) : ((u64)tgt << 32);
            if (__all_sync(0xFFFFFFFFu, (unsigned)(fv >> 32) >= tgt)) break;
        }
        // warp 0: S from the packed block sums (already in registers)
        if (wid == 0) {
            float bs = need ? __uint_as_float((unsigned)fv) : 0.f;
            #pragma unroll
            for (int o = 16; o; o >>= 1) bs += __shfl_xor_sync(0xFFFFFFFFu, bs, o);
            if (lane == 0) { s_S = bs; s_item = 0x7FFFFFFF; }
        }

        // all warps: load own p slice immediately, scan raw p (S-independent)
        int base8 = tid * 8;
        float4 pA = __ldcg((const float4*)(g_p[par] + base8));
        float4 pB = __ldcg((const float4*)(g_p[par] + base8 + 4));
        float q[8] = {pA.x, pA.y, pA.z, pA.w, pB.x, pB.y, pB.z, pB.w};
        float lq = ((q[0]+q[1])+(q[2]+q[3])) + ((q[4]+q[5])+(q[6]+q[7]));
        float inc = lq;
        #pragma unroll
        for (int o = 1; o < 32; o <<= 1) {
            float nv = __shfl_up_sync(0xFFFFFFFFu, inc, o);
            if (lane >= o) inc += nv;
        }
        float wexcl = inc - lq;
        if (lane == 31) swt[wid] = inc;
        __syncthreads();                      // swt + s_S + s_item init
        if (tid < 8) {
            float vv = swt[tid];
            float inc2 = vv;
            #pragma unroll
            for (int o = 1; o < 8; o <<= 1) {
                float nv = __shfl_up_sync(0xFFu, inc2, o);
                if (tid >= o) inc2 += nv;
            }
            swt2[tid] = inc2 - vv;
        }
        __syncthreads();

        // first index with cumsum(p) > u*S
        const float thr = u * s_S;
        float run = swt2[wid] + wexcl;
        int c = 0x7FFFFFFF;
        #pragma unroll
        for (int j = 0; j < 8; j++) {
            run += q[j];
            if (c == 0x7FFFFFFF && run > thr) c = base8 + j;
        }
        unsigned bm = __ballot_sync(0xFFFFFFFFu, c != 0x7FFFFFFF);
        if (bm && lane == __ffs(bm) - 1) atomicMin(&s_item, c);
        __syncthreads();
        int item = s_item;
        if (item == 0x7FFFFFFF) item = 0;     // argmax(all-False) -> 0
        if (bid == 0 && tid == 0) out[item] = 1.0f;

        if (m == 1) continue;   // reference keeps V unchanged when m==1; no publish

        // ---- a-row -> smem (float4, one RT) + n2 from published p[item] ----
        const float* arow = g_V[par] + (size_t)item * KM;
        if (tid < KM / 4) ((float4*)sa)[tid] = __ldcg((const float4*)arow + tid);
        float n2 = __ldcg(&g_p[par][item]);   // == ||a||^2 (published row norm)
        __syncthreads();
        float al  = sa[m - 1];
        float nrm = sqrtf(n2);
        float sh  = (al >= 0.f) ? nrm : -nrm;
        float den = fmaf(fabsf(al), nrm, n2); // ||u||^2 / 2
        float tau = (den > 0.f) ? (1.0f / den) : 0.f;

        // ---- Householder sweep, 2 threads/row (parity split), 4-way ILP ----
        {
            int pr = tid >> 1, h = tid & 1;
            int r = bid * RPB + pr;
            const float* vc = g_V[par] + (size_t)r * KM;
            float* vn = g_V[par ^ 1] + (size_t)r * KM;
            float t0 = 0.f, t1 = 0.f, t2 = 0.f, t3 = 0.f;
            int j = h;
            for (; j + 6 < m; j += 8) {
                t0 = fmaf(vc[j],     sa[j],     t0);
                t1 = fmaf(vc[j + 2], sa[j + 2], t1);
                t2 = fmaf(vc[j + 4], sa[j + 4], t2);
                t3 = fmaf(vc[j + 6], sa[j + 6], t3);
            }
            for (; j < m; j += 2) t0 = fmaf(vc[j], sa[j], t0);
            float t = (t0 + t1) + (t2 + t3);
            t += __shfl_xor_sync(0xFFFFFFFFu, t, 1);
            float w = tau * fmaf(sh, vc[m - 1], t);
            float a0 = 0.f, a1 = 0.f;
            j = h;
            for (; j + 2 < m - 1; j += 4) {
                float x0 = fmaf(-w, sa[j], vc[j]);         vn[j] = x0;     a0 = fmaf(x0, x0, a0);
                float x1 = fmaf(-w, sa[j + 2], vc[j + 2]); vn[j + 2] = x1; a1 = fmaf(x1, x1, a1);
            }
            for (; j < m - 1; j += 2) {
                float x = fmaf(-w, sa[j], vc[j]); vn[j] = x; a0 = fmaf(x, x, a0);
            }
            float acc = a0 + a1;
            float accT = acc + __shfl_xor_sync(0xFFFFFFFFu, acc, 1);
            if (h == 0) g_p[par ^ 1][r] = accT;
            float val = h ? 0.f : accT;
            #pragma unroll
            for (int o = 16; o; o >>= 1) val += __shfl_down_sync(0xFFFFFFFFu, val, o);
            if (lane == 0) swred[wid] = val;
        }
        __syncthreads();
        if (tid == 0) {
            float s = 0.f;
            #pragma unroll
            for (int w2 = 0; w2 < 8; w2++) s += swred[w2];
            st_rel64(&g_flag2[bid],
                     ((u64)(base + 2u + (unsigned)i) << 32) | (u64)__float_as_uint(s));
        }
    }

    // k == n -> all ones (concurrent writes are all 1.0f; benign)
    if (kfull == N) {
        if (tid < RPB) out[bid * RPB + tid] = 1.0f;
    }
}

extern "C" void kernel_launch(void* const* d_in, const int* in_sizes, int n_in,
                              void* d_out, int out_size) {
    const float* e    = (const float*)d_in[0];
    const float* v    = (const float*)d_in[1];
    const int*   seed = (const int*)d_in[2];
    (void)in_sizes; (void)n_in; (void)out_size;
    dpp_kernel<<<NB, T>>>(e, v, seed, (float*)d_out);
}

// round 9
// speedup vs baseline: 2.1164x; 1.3517x over previous
#include <cuda_runtime.h>
#include <cstdint>

#define N   2048
#define KM  192
#define NB  16
#define T   512
#define RPB (N/NB)   // 128 rows per block
#define NW  (T/32)   // 16 warps

typedef unsigned long long u64;

// ---------------- device state (no allocations allowed) ----------------
__device__ float g_V[2][N*KM];     // ping-pong basis, row-major stride KM
__device__ float g_p[2][N];        // ping-pong row norms^2
__device__ int   g_cols[KM];
__device__ int   g_k;
__device__ int   g_kk;
__device__ unsigned g_kl0, g_kl1;  // k_loop key
__device__ unsigned g_base;        // flag base for this launch
__device__ u64   g_flag2[NB];      // packed {counter:32, blocksum_bits:32}
__device__ unsigned g_arrive = 0;
__device__ volatile unsigned g_gen = 0;

// ---------------- acquire/release helpers ----------------
__device__ __forceinline__ u64 ld_acq64(const u64* p) {
    u64 v;
    asm volatile("ld.acquire.gpu.u64 %0, [%1];" : "=l"(v) : "l"(p) : "memory");
    return v;
}
__device__ __forceinline__ void st_rel64(u64* p, u64 v) {
    asm volatile("st.release.gpu.u64 [%0], %1;" :: "l"(p), "l"(v) : "memory");
}

// ---------------- threefry2x32 block (exact JAX rotation schedule) ----------------
__device__ __forceinline__ void tf2x32(unsigned k0, unsigned k1,
                                       unsigned c0, unsigned c1,
                                       unsigned &o0, unsigned &o1) {
    unsigned ks2 = k0 ^ k1 ^ 0x1BD11BDAu;
    unsigned x0 = c0 + k0, x1 = c1 + k1;
#define RR(r) { x0 += x1; x1 = (x1 << (r)) | (x1 >> (32 - (r))); x1 ^= x0; }
    RR(13) RR(15) RR(26) RR(6)   x0 += k1;  x1 += ks2 + 1u;
    RR(17) RR(29) RR(16) RR(24)  x0 += ks2; x1 += k0 + 2u;
    RR(13) RR(15) RR(26) RR(6)   x0 += k0;  x1 += k1 + 3u;
    RR(17) RR(29) RR(16) RR(24)  x0 += k1;  x1 += ks2 + 4u;
    RR(13) RR(15) RR(26) RR(6)   x0 += ks2; x1 += k0 + 5u;
#undef RR
    o0 = x0; o1 = x1;
}
__device__ __forceinline__ unsigned tf_bits32(unsigned k0, unsigned k1, unsigned i) {
    unsigned a, b;
    tf2x32(k0, k1, 0u, i, a, b);
    return a ^ b;
}
__device__ __forceinline__ float u01(unsigned b) {
    return __uint_as_float((b >> 9) | 0x3f800000u) - 1.0f;
}

// ---------------- one-time grid barrier (generation-based, replay-safe) ----------
__device__ __forceinline__ void grid_sync(unsigned &genL) {
    __syncthreads();
    if (threadIdx.x == 0) {
        __threadfence();
        unsigned t = atomicAdd(&g_arrive, 1u);
        if (t == NB - 1) {
            g_arrive = 0;
            __threadfence();
            g_gen = genL + 1;
        } else {
            while (g_gen == genL) { __nanosleep(32); }
        }
        __threadfence();
    }
    __syncthreads();
    genL++;
}

__global__ void __launch_bounds__(T, 1)
dpp_kernel(const float* __restrict__ e, const float* __restrict__ v,
           const int* __restrict__ seedp, float* __restrict__ out) {
    const int tid = threadIdx.x, bid = blockIdx.x;
    const int lane = tid & 31, wid = tid >> 5;

    __shared__ float sa[KM];
    __shared__ int   s_cols[KM];
    __shared__ float swred[NW];
    __shared__ float s_n2;
    __shared__ int   s_item;
    __shared__ unsigned s_k0, s_k1;
    __shared__ unsigned char sf[N];
    __shared__ int   sc[T];

    unsigned genL = g_gen;   // snapshot (read precedes our first arrive)

    // ---------------- phase 0: zero output, PRNG thinning, column compaction ----
    {
        int r0 = bid * RPB + tid;
        if (tid < RPB) out[r0] = 0.0f;
    }

    if (bid == 0) {
        if (tid == 0) {
            g_base = (unsigned)(g_flag2[0] >> 32);   // flags equal after any launch
            // jax.random.key(seed)=(0,seed); partitionable split: key_i = block(key,(0,i))
            unsigned key0 = 0u, key1 = (unsigned)seedp[0];
            unsigned a0, b0, a1, b1;
            tf2x32(key0, key1, 0u, 0u, a0, b0);   // k_idx
            tf2x32(key0, key1, 0u, 1u, a1, b1);   // k_loop
            s_k0 = a0; s_k1 = b0;
            g_kl0 = a1; g_kl1 = b1;
        }
        __syncthreads();
        unsigned kk0 = s_k0, kk1 = s_k1;
        for (int pp = tid; pp < N; pp += T) {
            float ev = e[pp];
            float thr = __fdiv_rn(ev, __fadd_rn(ev, 1.0f));
            sf[pp] = (u01(tf_bits32(kk0, kk1, (unsigned)pp)) < thr) ? 1 : 0;
        }
        __syncthreads();
        int base4 = tid * 4, cnt = 0;
        #pragma unroll
        for (int j = 0; j < 4; j++) cnt += sf[base4 + j];
        sc[tid] = cnt; __syncthreads();
        for (int off = 1; off < T; off <<= 1) {
            int val = sc[tid];
            int add = (tid >= off) ? sc[tid - off] : 0;
            __syncthreads();
            sc[tid] = val + add;
            __syncthreads();
        }
        int excl = sc[tid] - cnt, total = sc[T - 1];
        int pos = excl;
        for (int j = 0; j < 4; j++) {
            if (sf[base4 + j]) { if (pos < KM) g_cols[pos] = base4 + j; pos++; }
        }
        if (tid == 0) { g_k = total; g_kk = total < KM ? total : KM; }
    }

    grid_sync(genL);   // g_cols/g_kk/g_kl*/g_base visible

    const int kk = g_kk;
    const int kfull = g_k;
    const unsigned kl0 = g_kl0, kl1 = g_kl1;
    const unsigned base = g_base;

    for (int j = tid; j < KM; j += T) s_cols[j] = (j < kk) ? g_cols[j] : 0;
    __syncthreads();

    // ---------------- phase 1: gather V0 (4 threads/row) + p + publish ----------
    {
        int pr = tid >> 2, h = tid & 3;
        int r = bid * RPB + pr;
        const float* vr = v + (size_t)r * N;
        float* Vr = g_V[0] + (size_t)r * KM;
        float acc = 0.f;
        for (int j = h; j < kk; j += 4) {
            float x = vr[s_cols[j]];
            Vr[j] = x;
            acc = fmaf(x, x, acc);
        }
        float accT = acc;
        accT += __shfl_xor_sync(0xFFFFFFFFu, accT, 1);
        accT += __shfl_xor_sync(0xFFFFFFFFu, accT, 2);
        if (h == 0) g_p[0][r] = accT;
        float val = acc;               // raw per-thread; warp total = 8 row norms
        #pragma unroll
        for (int o = 16; o; o >>= 1) val += __shfl_down_sync(0xFFFFFFFFu, val, o);
        if (lane == 0) swred[wid] = val;
    }
    __syncthreads();
    if (wid == 0) {
        float s = (lane < NW) ? swred[lane] : 0.f;
        #pragma unroll
        for (int o = 8; o; o >>= 1) s += __shfl_xor_sync(0xFFFFFFFFu, s, o);
        if (lane == 0)
            st_rel64(&g_flag2[bid], ((u64)(base + 1u) << 32) | (u64)__float_as_uint(s));
    }

    // ---------------- main loop: warp0-only poll + hierarchical selection -------
    for (int i = 0; i < kk; i++) {
        const int m = kk - i;
        const int par = i & 1;

        if (wid == 0) {
            // u_i = uniform(fold_in(k_loop, i))
            unsigned f0, f1, w0, w1;
            tf2x32(kl0, kl1, 0u, (unsigned)i, f0, f1);
            tf2x32(f0, f1, 0u, 0u, w0, w1);
            const float u = u01(w0 ^ w1);

            // poll packed flags (acquire); payload = per-block sums
            const unsigned tgt = base + 1u + (unsigned)i;
            const bool need = lane < NB;
            u64 fv;
            for (;;) {
                fv = need ? ld_acq64(&g_flag2[lane]) : ((u64)tgt << 32);
                if (__all_sync(0xFFFFFFFFu, (unsigned)(fv >> 32) >= tgt)) break;
            }
            float sb = need ? __uint_as_float((unsigned)fv) : 0.f;

            // 16-lane inclusive scan of block sums
            float incl = sb;
            #pragma unroll
            for (int o = 1; o < 16; o <<= 1) {
                float nv = __shfl_up_sync(0xFFFFFFFFu, incl, o);
                if (lane >= o) incl += nv;
            }
            const float S = __shfl_sync(0xFFFFFFFFu, incl, 15);
            const float thr = u * S;

            unsigned bmB = __ballot_sync(0xFFFFFFFFu, need && incl > thr) & 0xFFFFu;
            int item; float n2;
            if (bmB == 0u) {
                item = 0;                                  // argmax(all-False) -> 0
                n2 = __ldcg(&g_p[par][0]);
            } else {
                int bstar = __ffs(bmB) - 1;
                float bexcl = __shfl_sync(0xFFFFFFFFu, incl - sb, bstar);
                // in-block: 128 p's, one float4 per lane
                float4 pv = __ldcg((const float4*)(g_p[par] + bstar * RPB) + lane);
                float ls = (pv.x + pv.y) + (pv.z + pv.w);
                float incl2 = ls;
                #pragma unroll
                for (int o = 1; o < 32; o <<= 1) {
                    float nv = __shfl_up_sync(0xFFFFFFFFu, incl2, o);
                    if (lane >= o) incl2 += nv;
                }
                float run = bexcl + (incl2 - ls);
                int c = 0x7FFFFFFF; float cn = 0.f;
                float qq[4] = {pv.x, pv.y, pv.z, pv.w};
                #pragma unroll
                for (int j = 0; j < 4; j++) {
                    run += qq[j];
                    if (c == 0x7FFFFFFF && run > thr) { c = lane * 4 + j; cn = qq[j]; }
                }
                unsigned bm2 = __ballot_sync(0xFFFFFFFFu, c != 0x7FFFFFFF);
                if (bm2) {
                    int l2 = __ffs(bm2) - 1;
                    item = bstar * RPB + __shfl_sync(0xFFFFFFFFu, c, l2);
                    n2   = __shfl_sync(0xFFFFFFFFu, cn, l2);
                } else {                                   // fp boundary fallback
                    item = bstar * RPB + RPB - 1;
                    n2   = __shfl_sync(0xFFFFFFFFu, pv.w, 31);
                }
            }
            if (lane == 0) {
                s_item = item; s_n2 = n2;
                if (bid == 0) out[item] = 1.0f;
            }
        }
        __syncthreads();                                   // item + causality to all warps
        const int item = s_item;

        if (m == 1) continue;   // reference keeps V unchanged when m==1; no publish

        // ---- a-row -> smem (float4 cooperative, one RT) ----
        const float* arow = g_V[par] + (size_t)item * KM;
        if (tid < KM / 4) ((float4*)sa)[tid] = __ldcg((const float4*)arow + tid);
        __syncthreads();
        const float n2  = s_n2;                            // == ||a||^2
        const float al  = sa[m - 1];
        const float nrm = sqrtf(n2);
        const float sh  = (al >= 0.f) ? nrm : -nrm;
        const float den = fmaf(fabsf(al), nrm, n2);        // ||u||^2 / 2
        const float tau = (den > 0.f) ? (1.0f / den) : 0.f;

        // ---- Householder sweep, 4 threads/row (quarter split), 2-way ILP ----
        {
            int pr = tid >> 2, h = tid & 3;
            int r = bid * RPB + pr;
            const float* vc = g_V[par] + (size_t)r * KM;
            float* vn = g_V[par ^ 1] + (size_t)r * KM;
            float t0 = 0.f, t1 = 0.f;
            int j = h;
            for (; j + 4 < m; j += 8) {
                t0 = fmaf(vc[j],     sa[j],     t0);
                t1 = fmaf(vc[j + 4], sa[j + 4], t1);
            }
            for (; j < m; j += 4) t0 = fmaf(vc[j], sa[j], t0);
            float t = t0 + t1;
            t += __shfl_xor_sync(0xFFFFFFFFu, t, 1);
            t += __shfl_xor_sync(0xFFFFFFFFu, t, 2);
            float w = tau * fmaf(sh, vc[m - 1], t);
            float acc = 0.f;
            for (j = h; j < m - 1; j += 4) {
                float x = fmaf(-w, sa[j], vc[j]);
                vn[j] = x;
                acc = fmaf(x, x, acc);
            }
            float accT = acc;
            accT += __shfl_xor_sync(0xFFFFFFFFu, accT, 1);
            accT += __shfl_xor_sync(0xFFFFFFFFu, accT, 2);
            if (h == 0) g_p[par ^ 1][r] = accT;
            float val = acc;
            #pragma unroll
            for (int o = 16; o; o >>= 1) val += __shfl_down_sync(0xFFFFFFFFu, val, o);
            if (lane == 0) swred[wid] = val;
        }
        __syncthreads();
        if (wid == 0) {
            float s = (lane < NW) ? swred[lane] : 0.f;
            #pragma unroll
            for (int o = 8; o; o >>= 1) s += __shfl_xor_sync(0xFFFFFFFFu, s, o);
            if (lane == 0)
                st_rel64(&g_flag2[bid],
                         ((u64)(base + 2u + (unsigned)i) << 32) | (u64)__float_as_uint(s));
        }
    }

    // k == n -> all ones (concurrent writes are all 1.0f; benign)
    if (kfull == N) {
        if (tid < RPB) out[bid * RPB + tid] = 1.0f;
    }
}

extern "C" void kernel_launch(void* const* d_in, const int* in_sizes, int n_in,
                              void* d_out, int out_size) {
    const float* e    = (const float*)d_in[0];
    const float* v    = (const float*)d_in[1];
    const int*   seed = (const int*)d_in[2];
    (void)in_sizes; (void)n_in; (void)out_size;
    dpp_kernel<<<NB, T>>>(e, v, seed, (float*)d_out);
}